// round 7
// baseline (speedup 1.0000x reference)
#include <cuda_runtime.h>

#define NEG_INF __int_as_float(0xff800000)

#define CS2 204   // float2 per c2 tile: 6 rows x 34 cols

// Exact fp32 max-plus conv.
// Block: 128 threads = 32 x-lanes x 4 y-rows. Thread: 2 o-channels, 1 (y,x).
// Grid: (o-pair=16, ytile=8, b=8) = 1024 blocks x 4 warps = 4096 warps (~27.7/SM).
// smem img: [c2=16][r=6][xx=34] float2 (channel pair) -> one LDS.64 feeds 2 channels.
// smem ker: [c2=16][p=9] float4 = (k[o0][c0], k[o1][c0], k[o0][c1], k[o1][c1]) at (2-dy,2-dx).
__global__ __launch_bounds__(128)
void bconv_kernel(const float* __restrict__ img,
                  const float* __restrict__ ker,
                  float* __restrict__ out)
{
    __shared__ float2 simg[16 * CS2];   // 26112 B
    __shared__ float4 sker[16 * 9];     //  2304 B

    const int o2  = blockIdx.x;         // 0..15
    const int yt  = blockIdx.y;         // 0..7
    const int b   = blockIdx.z;         // 0..7
    const int tid = threadIdx.x;
    const int x   = tid & 31;
    const int ty  = tid >> 5;           // 0..3
    const int y0  = yt * 4;

    const float2 ninf2 = make_float2(NEG_INF, NEG_INF);

    // ---- halo columns xx=0,33 (w=-1,32): always -inf. 16 c2 x 6 r x 2 = 192 ----
    if (tid < 128) {  // first 128 of 192
        int c2  = tid / 12;
        int rem = tid - c2 * 12;
        simg[c2 * CS2 + (rem >> 1) * 34 + ((rem & 1) ? 33 : 0)] = ninf2;
    } else { }
    {   // remaining 64 halo entries (tid 0..63 double-duty)
        int t = tid + 128;
        if (t < 192) {
            int c2  = t / 12;
            int rem = t - c2 * 12;
            simg[c2 * CS2 + (rem >> 1) * 34 + ((rem & 1) ? 33 : 0)] = ninf2;
        }
    }

    // ---- interior: 768 float4-tasks: c2 (16) x rr (6) x q (8) ----
    const float* gimg = img + b * 32768;
#pragma unroll
    for (int it = 0; it < 6; it++) {
        int t   = tid + it * 128;
        int c2  = t / 48;
        int rem = t - c2 * 48;
        int rr  = rem >> 3;
        int q   = rem & 7;
        int h   = y0 - 1 + rr;
        float2* sp = simg + c2 * CS2 + rr * 34 + 1 + q * 4;
        if ((unsigned)h < 32u) {
            const float4 a  = *(const float4*)(gimg + (c2 * 2)     * 1024 + h * 32 + q * 4);
            const float4 bb = *(const float4*)(gimg + (c2 * 2 + 1) * 1024 + h * 32 + q * 4);
            sp[0] = make_float2(a.x, bb.x);
            sp[1] = make_float2(a.y, bb.y);
            sp[2] = make_float2(a.z, bb.z);
            sp[3] = make_float2(a.w, bb.w);
        } else {
            sp[0] = ninf2; sp[1] = ninf2; sp[2] = ninf2; sp[3] = ninf2;
        }
    }

    // ---- kernel slice ----
    if (tid < 128) {
        int t = tid;
        // 144 entries; threads 0..127 do one, 0..15 do a second below
        int c2 = t / 9, p = t - c2 * 9;
        int dy = p / 3, dx = p - dy * 3;
        const float* kb = ker + (2 - dy) * 3 + (2 - dx);
        int c0 = c2 * 2, o0 = o2 * 2;
        sker[t] = make_float4(kb[((o0)     * 32 + c0)     * 9],
                              kb[((o0 + 1) * 32 + c0)     * 9],
                              kb[((o0)     * 32 + c0 + 1) * 9],
                              kb[((o0 + 1) * 32 + c0 + 1) * 9]);
    }
    if (tid < 16) {
        int t = tid + 128;
        int c2 = t / 9, p = t - c2 * 9;
        int dy = p / 3, dx = p - dy * 3;
        const float* kb = ker + (2 - dy) * 3 + (2 - dx);
        int c0 = c2 * 2, o0 = o2 * 2;
        sker[t] = make_float4(kb[((o0)     * 32 + c0)     * 9],
                              kb[((o0 + 1) * 32 + c0)     * 9],
                              kb[((o0)     * 32 + c0 + 1) * 9],
                              kb[((o0 + 1) * 32 + c0 + 1) * 9]);
    }
    __syncthreads();

    // 4 independent max chains: a{o}{parity}
    float a00 = NEG_INF, a01 = NEG_INF, a10 = NEG_INF, a11 = NEG_INF;

    const float2* vb = simg + ty * 34 + x;

#pragma unroll 2
    for (int c2 = 0; c2 < 16; c2++) {
        const float4* kp = sker + c2 * 9;
        float4 k[9];
#pragma unroll
        for (int p = 0; p < 9; p++) k[p] = kp[p];   // block-uniform broadcast LDS.128

        const float2* vp = vb + c2 * CS2;
        float2 v[9];
#pragma unroll
        for (int r = 0; r < 3; r++)
#pragma unroll
            for (int d = 0; d < 3; d++) v[r * 3 + d] = vp[r * 34 + d];

#pragma unroll
        for (int p = 0; p < 9; p++) {
            float s00 = v[p].x + k[p].x;   // o0, c even
            float s10 = v[p].x + k[p].y;   // o1, c even
            float s01 = v[p].y + k[p].z;   // o0, c odd
            float s11 = v[p].y + k[p].w;   // o1, c odd
            if (p & 1) {
                a01 = fmaxf(a01, s00); a11 = fmaxf(a11, s10);
                a00 = fmaxf(a00, s01); a10 = fmaxf(a10, s11);
            } else {
                a00 = fmaxf(a00, s00); a10 = fmaxf(a10, s10);
                a01 = fmaxf(a01, s01); a11 = fmaxf(a11, s11);
            }
        }
    }

    float* gout = out + ((b * 32 + o2 * 2) * 32 + (y0 + ty)) * 32 + x;
    gout[0]    = fmaxf(a00, a01);
    gout[1024] = fmaxf(a10, a11);
}

extern "C" void kernel_launch(void* const* d_in, const int* in_sizes, int n_in,
                              void* d_out, int out_size)
{
    const float* img = (const float*)d_in[0];
    const float* ker = (const float*)d_in[1];
    float*       out = (float*)d_out;
    dim3 grid(16, 8, 8);   // (o-pair, ytile, batch)
    bconv_kernel<<<grid, 128>>>(img, ker, out);
}

// round 8
// speedup vs baseline: 1.1123x; 1.1123x over previous
#include <cuda_runtime.h>

#define NEG_INF __int_as_float(0xff800000)

#define RS 34          // float2 row stride
#define CS2 340        // float2 per c2 tile: 10 rows x 34

// Exact fp32 max-plus conv, y-blocked.
// Block: 128 threads = 32 x-lanes x 4 ty. Thread: 2 o-channels x 2 y-rows (4 outputs).
// Grid: (o-pair=16, ytile=4, b=8) = 512 blocks x 4 warps = 2048 warps (~13.8/SM).
// smem img: [c2=16][r=10][xx=34] float2 (channel pair); rows cover y0-1 .. y0+8.
// smem ker: [c2=16][p=9] float4 = (k[o0][c0], k[o1][c0], k[o0][c1], k[o1][c1]) at (2-dy,2-dx).
__global__ __launch_bounds__(128)
void bconv_kernel(const float* __restrict__ img,
                  const float* __restrict__ ker,
                  float* __restrict__ out)
{
    __shared__ float2 simg[16 * CS2];   // 43520 B
    __shared__ float4 sker[16 * 9];     //  2304 B

    const int o2  = blockIdx.x;         // 0..15
    const int yt  = blockIdx.y;         // 0..3
    const int b   = blockIdx.z;         // 0..7
    const int tid = threadIdx.x;
    const int x   = tid & 31;
    const int ty  = tid >> 5;           // 0..3
    const int y0  = yt * 8;

    const float2 ninf2 = make_float2(NEG_INF, NEG_INF);

    // ---- halo columns xx=0,33 (w=-1,32): always -inf. 16 c2 x 10 r x 2 = 320 ----
#pragma unroll
    for (int it = 0; it < 3; it++) {
        int t = tid + it * 128;
        if (t < 320) {
            int c2  = t / 20;
            int rem = t - c2 * 20;
            simg[c2 * CS2 + (rem >> 1) * RS + ((rem & 1) ? 33 : 0)] = ninf2;
        }
    }

    // ---- interior: 1280 float4-tasks: c2(16) x rr(10) x q(8) ----
    const float* gimg = img + b * 32768;
#pragma unroll
    for (int it = 0; it < 10; it++) {
        int t   = tid + it * 128;
        int c2  = t / 80;
        int rem = t - c2 * 80;
        int rr  = rem >> 3;
        int q   = rem & 7;
        int h   = y0 - 1 + rr;
        float2* sp = simg + c2 * CS2 + rr * RS + 1 + q * 4;
        if ((unsigned)h < 32u) {
            const float4 a  = *(const float4*)(gimg + (c2 * 2)     * 1024 + h * 32 + q * 4);
            const float4 bb = *(const float4*)(gimg + (c2 * 2 + 1) * 1024 + h * 32 + q * 4);
            sp[0] = make_float2(a.x, bb.x);
            sp[1] = make_float2(a.y, bb.y);
            sp[2] = make_float2(a.z, bb.z);
            sp[3] = make_float2(a.w, bb.w);
        } else {
            sp[0] = ninf2; sp[1] = ninf2; sp[2] = ninf2; sp[3] = ninf2;
        }
    }

    // ---- kernel slice: sker[c2*9+p] = (k[o0][c0], k[o1][c0], k[o0][c1], k[o1][c1]) at (2-dy,2-dx) ----
    {
        int t = tid;
        int c2 = t / 9, p = t - c2 * 9;
        int dy = p / 3, dx = p - dy * 3;
        const float* kb = ker + (2 - dy) * 3 + (2 - dx);
        int c0 = c2 * 2, o0 = o2 * 2;
        sker[t] = make_float4(kb[((o0)     * 32 + c0)     * 9],
                              kb[((o0 + 1) * 32 + c0)     * 9],
                              kb[((o0)     * 32 + c0 + 1) * 9],
                              kb[((o0 + 1) * 32 + c0 + 1) * 9]);
    }
    if (tid < 16) {
        int t = tid + 128;
        int c2 = t / 9, p = t - c2 * 9;
        int dy = p / 3, dx = p - dy * 3;
        const float* kb = ker + (2 - dy) * 3 + (2 - dx);
        int c0 = c2 * 2, o0 = o2 * 2;
        sker[t] = make_float4(kb[((o0)     * 32 + c0)     * 9],
                              kb[((o0 + 1) * 32 + c0)     * 9],
                              kb[((o0)     * 32 + c0 + 1) * 9],
                              kb[((o0 + 1) * 32 + c0 + 1) * 9]);
    }
    __syncthreads();

    // 8 independent max chains: acc[yy][o][parity]
    float a000 = NEG_INF, a001 = NEG_INF, a010 = NEG_INF, a011 = NEG_INF;
    float a100 = NEG_INF, a101 = NEG_INF, a110 = NEG_INF, a111 = NEG_INF;

    // thread rows: tile rows ty*2 .. ty*2+3 (outputs y0+ty*2, y0+ty*2+1)
    const float2* vb = simg + (ty * 2) * RS + x;

#pragma unroll 1
    for (int c2 = 0; c2 < 16; c2++) {
        const float4* kp = sker + c2 * 9;
        float4 k[9];
#pragma unroll
        for (int p = 0; p < 9; p++) k[p] = kp[p];     // block-uniform broadcast

        const float2* vp = vb + c2 * CS2;
        float2 v[4][3];
#pragma unroll
        for (int r = 0; r < 4; r++)
#pragma unroll
            for (int d = 0; d < 3; d++) v[r][d] = vp[r * RS + d];

#pragma unroll
        for (int p = 0; p < 9; p++) {
            const int dy = p / 3, dx = p - dy * 3;
            const float2 v0 = v[dy][dx];       // for yy=0
            const float2 v1 = v[dy + 1][dx];   // for yy=1
            float s000 = v0.x + k[p].x, s010 = v0.x + k[p].y;
            float s001 = v0.y + k[p].z, s011 = v0.y + k[p].w;
            float s100 = v1.x + k[p].x, s110 = v1.x + k[p].y;
            float s101 = v1.y + k[p].z, s111 = v1.y + k[p].w;
            if (p & 1) {
                a001 = fmaxf(a001, s000); a011 = fmaxf(a011, s010);
                a000 = fmaxf(a000, s001); a010 = fmaxf(a010, s011);
                a101 = fmaxf(a101, s100); a111 = fmaxf(a111, s110);
                a100 = fmaxf(a100, s101); a110 = fmaxf(a110, s111);
            } else {
                a000 = fmaxf(a000, s000); a010 = fmaxf(a010, s010);
                a001 = fmaxf(a001, s001); a011 = fmaxf(a011, s011);
                a100 = fmaxf(a100, s100); a110 = fmaxf(a110, s110);
                a101 = fmaxf(a101, s101); a111 = fmaxf(a111, s111);
            }
        }
    }

    const int yb = y0 + ty * 2;
    float* gout = out + ((b * 32 + o2 * 2) * 32 + yb) * 32 + x;
    gout[0]        = fmaxf(a000, a001);   // o0, yy0
    gout[32]       = fmaxf(a100, a101);   // o0, yy1
    gout[1024]     = fmaxf(a010, a011);   // o1, yy0
    gout[1024+32]  = fmaxf(a110, a111);   // o1, yy1
}

extern "C" void kernel_launch(void* const* d_in, const int* in_sizes, int n_in,
                              void* d_out, int out_size)
{
    const float* img = (const float*)d_in[0];
    const float* ker = (const float*)d_in[1];
    float*       out = (float*)d_out;
    dim3 grid(16, 4, 8);   // (o-pair, ytile, batch)
    bconv_kernel<<<grid, 128>>>(img, ker, out);
}

// round 9
// speedup vs baseline: 1.1146x; 1.0021x over previous
#include <cuda_runtime.h>

#define NEG_INF __int_as_float(0xff800000)

#define RS 34          // float2 per smem img row
#define CS2 340        // float2 per c2 tile: 10 rows x 34

// Exact fp32 max-plus conv; x-blocked LDS.128, og-dedup v loads.
// Block: 128 threads = 16 xl x 2 og x 4 typ. Thread: 1 o x 2 x x 2 y (4 outputs).
// Grid: (o-pair=16, ytile=4, b=8) = 512 blocks x 4 warps = 2048 warps (~13.8/SM).
// smem img: [c2=16][r=10][xx=34] float2 (channel pair), rows = y0-1 .. y0+8.
// smem ker: [c2=16][og=2][p pad 10] float2 = (k[o][c0],k[o][c1]) at (2-dy,2-dx).
__global__ __launch_bounds__(128)
void bconv_kernel(const float* __restrict__ img,
                  const float* __restrict__ ker,
                  float* __restrict__ out)
{
    __shared__ __align__(16) float2 simg[16 * CS2];   // 43520 B
    __shared__ __align__(16) float2 sker[16 * 2 * 10]; //  2560 B

    const int o2  = blockIdx.x;        // 0..15
    const int yt  = blockIdx.y;        // 0..3
    const int b   = blockIdx.z;        // 0..7
    const int tid = threadIdx.x;
    const int xl  = tid & 15;          // x0 = 2*xl
    const int og  = (tid >> 4) & 1;    // which o of the pair
    const int typ = tid >> 5;          // 0..3 (y pair)
    const int y0  = yt * 8;

    const float2 ninf2 = make_float2(NEG_INF, NEG_INF);

    // ---- halo columns xx=0,33 (w=-1,32): always -inf. 16 c2 x 10 r x 2 = 320 ----
#pragma unroll
    for (int it = 0; it < 3; it++) {
        int t = tid + it * 128;
        if (t < 320) {
            int c2  = t / 20;
            int rem = t - c2 * 20;
            simg[c2 * CS2 + (rem >> 1) * RS + ((rem & 1) ? 33 : 0)] = ninf2;
        }
    }

    // ---- interior: 1280 float4-tasks: c2(16) x rr(10) x q(8) ----
    const float* gimg = img + b * 32768;
#pragma unroll
    for (int it = 0; it < 10; it++) {
        int t   = tid + it * 128;
        int c2  = t / 80;
        int rem = t - c2 * 80;
        int rr  = rem >> 3;
        int q   = rem & 7;
        int h   = y0 - 1 + rr;
        float2* sp = simg + c2 * CS2 + rr * RS + 1 + q * 4;
        if ((unsigned)h < 32u) {
            const float4 a  = *(const float4*)(gimg + (c2 * 2)     * 1024 + h * 32 + q * 4);
            const float4 bb = *(const float4*)(gimg + (c2 * 2 + 1) * 1024 + h * 32 + q * 4);
            sp[0] = make_float2(a.x, bb.x);
            sp[1] = make_float2(a.y, bb.y);
            sp[2] = make_float2(a.z, bb.z);
            sp[3] = make_float2(a.w, bb.w);
        } else {
            sp[0] = ninf2; sp[1] = ninf2; sp[2] = ninf2; sp[3] = ninf2;
        }
    }

    // ---- kernel slice: 288 entries: c2(16) x og(2) x p(9) ----
#pragma unroll
    for (int it = 0; it < 3; it++) {
        int t = tid + it * 128;
        if (t < 288) {
            int c2  = t / 18;
            int rem = t - c2 * 18;
            int g   = rem / 9;
            int p   = rem - g * 9;
            int dy  = p / 3, dx = p - dy * 3;
            const float* kb = ker + (2 - dy) * 3 + (2 - dx);
            int o = o2 * 2 + g, c0 = c2 * 2;
            sker[(c2 * 2 + g) * 10 + p] =
                make_float2(kb[(o * 32 + c0) * 9], kb[(o * 32 + c0 + 1) * 9]);
        }
    }
    __syncthreads();

    // 8 max chains: a[cpar*4 + yy*2 + xi]
    float a[8];
#pragma unroll
    for (int i = 0; i < 8; i++) a[i] = NEG_INF;

    const float2* vb = simg + (typ * 2) * RS + 2 * xl;
    const float2* kb2 = sker + og * 10;

#pragma unroll 1
    for (int c2 = 0; c2 < 16; c2++) {
        // k: 4x LDS.128 + 1x LDS.64 (2 distinct addrs per warp -> 1 wf each)
        const float4* kp4 = (const float4*)(kb2 + c2 * 20);
        float4 kA = kp4[0], kB = kp4[1], kC = kp4[2], kD = kp4[3];
        float2 kE = kb2[c2 * 20 + 8];
        float2 k[9];
        k[0] = make_float2(kA.x, kA.y); k[1] = make_float2(kA.z, kA.w);
        k[2] = make_float2(kB.x, kB.y); k[3] = make_float2(kB.z, kB.w);
        k[4] = make_float2(kC.x, kC.y); k[5] = make_float2(kC.z, kC.w);
        k[6] = make_float2(kD.x, kD.y); k[7] = make_float2(kD.z, kD.w);
        k[8] = kE;

        // v: 4 rows x 2 LDS.128 (og halves share addrs -> dedup)
        const float2* vp = vb + c2 * CS2;
        float2 w[4][4];
#pragma unroll
        for (int r = 0; r < 4; r++) {
            float4 A = *(const float4*)(vp + r * RS);
            float4 B = *(const float4*)(vp + r * RS + 2);
            w[r][0] = make_float2(A.x, A.y); w[r][1] = make_float2(A.z, A.w);
            w[r][2] = make_float2(B.x, B.y); w[r][3] = make_float2(B.z, B.w);
        }

#pragma unroll
        for (int p = 0; p < 9; p++) {
            const int dy = p / 3, dx = p - dy * 3;
            const float2 kk = k[p];
#pragma unroll
            for (int yy = 0; yy < 2; yy++) {
                const float2 v0 = w[dy + yy][dx];       // output x0
                const float2 v1 = w[dy + yy][dx + 1];   // output x0+1
                a[yy * 2 + 0]     = fmaxf(a[yy * 2 + 0],     v0.x + kk.x);
                a[yy * 2 + 1]     = fmaxf(a[yy * 2 + 1],     v1.x + kk.x);
                a[4 + yy * 2 + 0] = fmaxf(a[4 + yy * 2 + 0], v0.y + kk.y);
                a[4 + yy * 2 + 1] = fmaxf(a[4 + yy * 2 + 1], v1.y + kk.y);
            }
        }
    }

    // ---- combine c-parity chains; store float2 per y ----
    const int o = o2 * 2 + og;
    const int yb = y0 + typ * 2;
    float2* gout = (float2*)(out + ((b * 32 + o) * 32 + yb) * 32 + 2 * xl);
#pragma unroll
    for (int yy = 0; yy < 2; yy++) {
        float2 r;
        r.x = fmaxf(a[yy * 2 + 0], a[4 + yy * 2 + 0]);
        r.y = fmaxf(a[yy * 2 + 1], a[4 + yy * 2 + 1]);
        gout[yy * 16] = r;   // +32 floats = next y row
    }
}

extern "C" void kernel_launch(void* const* d_in, const int* in_sizes, int n_in,
                              void* d_out, int out_size)
{
    const float* img = (const float*)d_in[0];
    const float* ker = (const float*)d_in[1];
    float*       out = (float*)d_out;
    dim3 grid(16, 4, 8);   // (o-pair, ytile, batch)
    bconv_kernel<<<grid, 128>>>(img, ker, out);
}

// round 10
// speedup vs baseline: 1.1932x; 1.0705x over previous
#include <cuda_runtime.h>

#define NEG_INF __int_as_float(0xff800000)

typedef unsigned long long ull;

#define RS 34          // float2 per smem img row
#define CS2 340        // float2 per c2 tile: 10 rows x 34

// packed f32x2 add + unpack halves (unpack = register aliasing, free in SASS)
#define ADDU(LO, HI, V, K)                                                  \
    asm("{\n\t.reg .b64 t;\n\tadd.rn.f32x2 t, %2, %3;\n\tmov.b64 {%0,%1}, t;\n\t}" \
        : "=f"(LO), "=f"(HI) : "l"(V), "l"(K))

// Exact fp32 max-plus conv; f32x2 packed adds over channel pairs; c-split halves.
// Block: 256 threads = 2 ch-halves x (16 xl x 2 og x 4 typ).
// Thread: 1 o x 2 x x 2 y over 8 of 16 c2; halves combined via smem.
// Grid: (o-pair=16, ytile=4, b=8) = 512 blocks x 8 warps = 4096 warps (~27.7/SM).
__global__ __launch_bounds__(256)
void bconv_kernel(const float* __restrict__ img,
                  const float* __restrict__ ker,
                  float* __restrict__ out)
{
    __shared__ __align__(16) float2 simg[16 * CS2];    // 43520 B (reused for combine)
    __shared__ __align__(16) float2 sker[16 * 2 * 10]; //  2560 B

    const int o2   = blockIdx.x;         // 0..15
    const int yt   = blockIdx.y;         // 0..3
    const int b    = blockIdx.z;         // 0..7
    const int tid  = threadIdx.x;
    const int ch   = tid >> 7;           // c-half: 0 or 1
    const int tidL = tid & 127;
    const int xl   = tidL & 15;          // x0 = 2*xl
    const int og   = (tidL >> 4) & 1;    // which o of the pair
    const int typ  = tidL >> 5;          // 0..3 (y pair)
    const int y0   = yt * 8;

    const float2 ninf2 = make_float2(NEG_INF, NEG_INF);

    // ---- halo columns xx=0,33 (w=-1,32): always -inf. 320 entries ----
#pragma unroll
    for (int it = 0; it < 2; it++) {
        int t = tid + it * 256;
        if (t < 320) {
            int c2  = t / 20;
            int rem = t - c2 * 20;
            simg[c2 * CS2 + (rem >> 1) * RS + ((rem & 1) ? 33 : 0)] = ninf2;
        }
    }

    // ---- interior: 1280 float4-tasks: c2(16) x rr(10) x q(8) ----
    const float* gimg = img + b * 32768;
#pragma unroll
    for (int it = 0; it < 5; it++) {
        int t   = tid + it * 256;
        int c2  = t / 80;
        int rem = t - c2 * 80;
        int rr  = rem >> 3;
        int q   = rem & 7;
        int h   = y0 - 1 + rr;
        float2* sp = simg + c2 * CS2 + rr * RS + 1 + q * 4;
        if ((unsigned)h < 32u) {
            const float4 a  = *(const float4*)(gimg + (c2 * 2)     * 1024 + h * 32 + q * 4);
            const float4 bb = *(const float4*)(gimg + (c2 * 2 + 1) * 1024 + h * 32 + q * 4);
            sp[0] = make_float2(a.x, bb.x);
            sp[1] = make_float2(a.y, bb.y);
            sp[2] = make_float2(a.z, bb.z);
            sp[3] = make_float2(a.w, bb.w);
        } else {
            sp[0] = ninf2; sp[1] = ninf2; sp[2] = ninf2; sp[3] = ninf2;
        }
    }

    // ---- kernel slice: 288 entries: c2(16) x og(2) x p(9) ----
#pragma unroll
    for (int it = 0; it < 2; it++) {
        int t = tid + it * 256;
        if (t < 288) {
            int c2  = t / 18;
            int rem = t - c2 * 18;
            int g   = rem / 9;
            int p   = rem - g * 9;
            int dy  = p / 3, dx = p - dy * 3;
            const float* kb = ker + (2 - dy) * 3 + (2 - dx);
            int o = o2 * 2 + g, c0 = c2 * 2;
            sker[(c2 * 2 + g) * 10 + p] =
                make_float2(kb[(o * 32 + c0) * 9], kb[(o * 32 + c0 + 1) * 9]);
        }
    }
    __syncthreads();

    // 8 chains: a[cpar*4 + yy*2 + xi]
    float a[8];
#pragma unroll
    for (int i = 0; i < 8; i++) a[i] = NEG_INF;

    const float2* vb  = simg + (typ * 2) * RS + 2 * xl;
    const float2* kb2 = sker + og * 10;

#pragma unroll 1
    for (int i = 0; i < 8; i++) {
        const int c2 = ch * 8 + i;

        // k: 9 packed (c0,c1) pairs, block-half-uniform broadcast
        const ulonglong2* kp = (const ulonglong2*)(kb2 + c2 * 20);
        ulonglong2 q0 = kp[0], q1 = kp[1], q2 = kp[2], q3 = kp[3];
        ull k8 = *(const ull*)(kb2 + c2 * 20 + 8);
        ull k[9];
        k[0] = q0.x; k[1] = q0.y; k[2] = q1.x; k[3] = q1.y;
        k[4] = q2.x; k[5] = q2.y; k[6] = q3.x; k[7] = q3.y; k[8] = k8;

        // v: 4 rows x 4 packed channel-pairs (og halves share addrs)
        const float2* vp = vb + c2 * CS2;
        ull w[4][4];
#pragma unroll
        for (int r = 0; r < 4; r++) {
            ulonglong2 A = *(const ulonglong2*)(vp + r * RS);
            ulonglong2 B = *(const ulonglong2*)(vp + r * RS + 2);
            w[r][0] = A.x; w[r][1] = A.y; w[r][2] = B.x; w[r][3] = B.y;
        }

#pragma unroll
        for (int p = 0; p < 9; p++) {
            const int dy = p / 3, dx = p - dy * 3;
            const ull kk = k[p];
#pragma unroll
            for (int yy = 0; yy < 2; yy++) {
                float lo0, hi0, lo1, hi1;
                ADDU(lo0, hi0, w[dy + yy][dx],     kk);   // output x0:   (c even, c odd)
                ADDU(lo1, hi1, w[dy + yy][dx + 1], kk);   // output x0+1
                a[yy * 2 + 0]     = fmaxf(a[yy * 2 + 0],     lo0);
                a[4 + yy * 2 + 0] = fmaxf(a[4 + yy * 2 + 0], hi0);
                a[yy * 2 + 1]     = fmaxf(a[yy * 2 + 1],     lo1);
                a[4 + yy * 2 + 1] = fmaxf(a[4 + yy * 2 + 1], hi1);
            }
        }
    }

    // ---- fold c-parity chains -> r[yy][xi] ----
    float r00 = fmaxf(a[0], a[4]);
    float r01 = fmaxf(a[1], a[5]);
    float r10 = fmaxf(a[2], a[6]);
    float r11 = fmaxf(a[3], a[7]);

    // ---- combine the two c-halves through smem (overlay on simg) ----
    __syncthreads();                       // all simg reads done
    float4* scomb = (float4*)simg;
    if (ch == 1) scomb[tidL] = make_float4(r00, r01, r10, r11);
    __syncthreads();
    if (ch == 0) {
        float4 oth = scomb[tidL];
        r00 = fmaxf(r00, oth.x); r01 = fmaxf(r01, oth.y);
        r10 = fmaxf(r10, oth.z); r11 = fmaxf(r11, oth.w);

        const int o  = o2 * 2 + og;
        const int yb = y0 + typ * 2;
        float2* gout = (float2*)(out + ((b * 32 + o) * 32 + yb) * 32 + 2 * xl);
        gout[0]  = make_float2(r00, r01);
        gout[16] = make_float2(r10, r11);   // next y row (+32 floats)
    }
}

extern "C" void kernel_launch(void* const* d_in, const int* in_sizes, int n_in,
                              void* d_out, int out_size)
{
    const float* img = (const float*)d_in[0];
    const float* ker = (const float*)d_in[1];
    float*       out = (float*)d_out;
    dim3 grid(16, 4, 8);   // (o-pair, ytile, batch)
    bconv_kernel<<<grid, 256>>>(img, ker, out);
}